// round 1
// baseline (speedup 1.0000x reference)
#include <cuda_runtime.h>

#define D_MODEL 1024
#define BM 128
#define BN 128
#define BK 8
#define TM 8
#define TN 8
#define MAX_ROWS 16384

// Ping-pong scratch (allocation-free rule: __device__ globals)
__device__ float g_buf0[MAX_ROWS * D_MODEL];
__device__ float g_buf1[MAX_ROWS * D_MODEL];

// ---------------- packed fp32x2 helpers (Blackwell FFMA2 path) ----------------
__device__ __forceinline__ unsigned long long ffma2(unsigned long long a,
                                                    unsigned long long b,
                                                    unsigned long long c) {
    unsigned long long d;
    asm("fma.rn.f32x2 %0, %1, %2, %3;" : "=l"(d) : "l"(a), "l"(b), "l"(c));
    return d;
}
__device__ __forceinline__ unsigned long long pack2(float lo, float hi) {
    unsigned long long r;
    asm("mov.b64 %0, {%1, %2};" : "=l"(r) : "f"(lo), "f"(hi));
    return r;
}
__device__ __forceinline__ float2 unpack2(unsigned long long v) {
    float lo, hi;
    asm("mov.b64 {%0, %1}, %2;" : "=f"(lo), "=f"(hi) : "l"(v));
    return make_float2(lo, hi);
}

__device__ __forceinline__ float silu(float x) {
    return x * (1.0f / (1.0f + __expf(-x)));
}

// ---------------- GEMM: C[M,N] = A[M,K] @ B[K,N] + bias, optional SiLU ----------------
// A row-major, B row-major (weights are (d_in, d_out) per the einsum "bsd,de->bse").
// 256 threads, 128x128 tile, 8x8 per thread, accumulators as f32x2 pairs.
template <int ACT>  // 0 = none, 1 = silu
__global__ __launch_bounds__(256)
void gemm_bias_act(const float* __restrict__ A, const float* __restrict__ B,
                   const float* __restrict__ bias, float* __restrict__ C,
                   int M, int N, int K) {
    __shared__ float As[BK][BM];   // transposed A tile
    __shared__ float Bs[BK][BN];

    const int tid = threadIdx.x;
    const int tx = tid & 15;       // 0..15 -> column group
    const int ty = tid >> 4;       // 0..15 -> row group
    const int bm = blockIdx.y * BM;
    const int bn = blockIdx.x * BN;

    // A tile load: 128 rows x 8 cols, 2 threads per row (float4 each)
    const int arow = tid >> 1;
    const int acol = (tid & 1) * 4;
    // B tile load: 8 rows x 128 cols, 32 threads per row (float4 each)
    const int brow = tid >> 5;
    const int bcol = (tid & 31) * 4;

    const float* Aptr = A + (size_t)(bm + arow) * K + acol;
    const float* Bptr = B + (size_t)brow * N + bn + bcol;

    unsigned long long acc[TM][TN / 2];
#pragma unroll
    for (int i = 0; i < TM; i++)
#pragma unroll
        for (int j = 0; j < TN / 2; j++) acc[i][j] = 0ull;

    for (int k0 = 0; k0 < K; k0 += BK) {
        const float4 av = *(const float4*)(Aptr + k0);
        const float4 bv = *(const float4*)(Bptr + (size_t)k0 * N);
        __syncthreads();   // previous tile's compute done before overwrite
        As[acol + 0][arow] = av.x;
        As[acol + 1][arow] = av.y;
        As[acol + 2][arow] = av.z;
        As[acol + 3][arow] = av.w;
        *(float4*)&Bs[brow][bcol] = bv;
        __syncthreads();

#pragma unroll
        for (int k = 0; k < BK; k++) {
            const float4 a0 = *(const float4*)&As[k][ty * TM];
            const float4 a1 = *(const float4*)&As[k][ty * TM + 4];
            const ulonglong2 bp0 = *(const ulonglong2*)&Bs[k][tx * TN];
            const ulonglong2 bp1 = *(const ulonglong2*)&Bs[k][tx * TN + 4];

            unsigned long long ad[TM];
            ad[0] = pack2(a0.x, a0.x);
            ad[1] = pack2(a0.y, a0.y);
            ad[2] = pack2(a0.z, a0.z);
            ad[3] = pack2(a0.w, a0.w);
            ad[4] = pack2(a1.x, a1.x);
            ad[5] = pack2(a1.y, a1.y);
            ad[6] = pack2(a1.z, a1.z);
            ad[7] = pack2(a1.w, a1.w);
#pragma unroll
            for (int i = 0; i < TM; i++) {
                acc[i][0] = ffma2(ad[i], bp0.x, acc[i][0]);
                acc[i][1] = ffma2(ad[i], bp0.y, acc[i][1]);
                acc[i][2] = ffma2(ad[i], bp1.x, acc[i][2]);
                acc[i][3] = ffma2(ad[i], bp1.y, acc[i][3]);
            }
        }
    }

    // Epilogue: bias (+ optional SiLU), vectorized stores
    const int col = bn + tx * TN;
    const float4 bias0 = *(const float4*)&bias[col];
    const float4 bias1 = *(const float4*)&bias[col + 4];

#pragma unroll
    for (int i = 0; i < TM; i++) {
        const int row = bm + ty * TM + i;
        float2 v0 = unpack2(acc[i][0]);
        float2 v1 = unpack2(acc[i][1]);
        float2 v2 = unpack2(acc[i][2]);
        float2 v3 = unpack2(acc[i][3]);
        float4 o0 = make_float4(v0.x + bias0.x, v0.y + bias0.y,
                                v1.x + bias0.z, v1.y + bias0.w);
        float4 o1 = make_float4(v2.x + bias1.x, v2.y + bias1.y,
                                v3.x + bias1.z, v3.y + bias1.w);
        if (ACT == 1) {
            o0.x = silu(o0.x); o0.y = silu(o0.y); o0.z = silu(o0.z); o0.w = silu(o0.w);
            o1.x = silu(o1.x); o1.y = silu(o1.y); o1.z = silu(o1.z); o1.w = silu(o1.w);
        }
        float* crow = C + (size_t)row * N + col;
        *(float4*)crow = o0;
        *(float4*)(crow + 4) = o1;
    }
}

// ---------------- LayerNorm over last dim (D=1024), eps=1e-5, no scale/bias ----------------
__global__ __launch_bounds__(256)
void layernorm_kernel(const float* __restrict__ in, float* __restrict__ out) {
    __shared__ float2 red[8];
    const int row = blockIdx.x;
    const int tid = threadIdx.x;

    const float4 v = *(const float4*)(in + (size_t)row * D_MODEL + tid * 4);
    float s  = v.x + v.y + v.z + v.w;
    float ss = v.x * v.x + v.y * v.y + v.z * v.z + v.w * v.w;

#pragma unroll
    for (int o = 16; o > 0; o >>= 1) {
        s  += __shfl_xor_sync(0xFFFFFFFFu, s,  o);
        ss += __shfl_xor_sync(0xFFFFFFFFu, ss, o);
    }
    if ((tid & 31) == 0) red[tid >> 5] = make_float2(s, ss);
    __syncthreads();
    if (tid < 32) {
        float2 r = (tid < 8) ? red[tid] : make_float2(0.0f, 0.0f);
        s = r.x; ss = r.y;
#pragma unroll
        for (int o = 4; o > 0; o >>= 1) {
            s  += __shfl_xor_sync(0xFFFFFFFFu, s,  o);
            ss += __shfl_xor_sync(0xFFFFFFFFu, ss, o);
        }
        if (tid == 0) red[0] = make_float2(s, ss);
    }
    __syncthreads();

    const float inv_d = 1.0f / (float)D_MODEL;
    const float mu  = red[0].x * inv_d;
    const float var = red[0].y * inv_d - mu * mu;
    const float r   = rsqrtf(var + 1e-5f);

    float4 o4 = make_float4((v.x - mu) * r, (v.y - mu) * r,
                            (v.z - mu) * r, (v.w - mu) * r);
    *(float4*)(out + (size_t)row * D_MODEL + tid * 4) = o4;
}

// ---------------- launch ----------------
extern "C" void kernel_launch(void* const* d_in, const int* in_sizes, int n_in,
                              void* d_out, int out_size) {
    const float* x     = (const float*)d_in[0];
    const float* wq    = (const float*)d_in[1];
    const float* bq    = (const float*)d_in[2];
    const float* mlp_w = (const float*)d_in[3];
    const float* mlp_b = (const float*)d_in[4];
    const float* w_out = (const float*)d_in[5];
    const float* b_out = (const float*)d_in[6];
    float* out = (float*)d_out;

    const int M = in_sizes[0] / D_MODEL;   // 16384
    const int N = D_MODEL, K = D_MODEL;
    const size_t DD = (size_t)D_MODEL * D_MODEL;

    float *buf0, *buf1;
    cudaGetSymbolAddress((void**)&buf0, g_buf0);
    cudaGetSymbolAddress((void**)&buf1, g_buf1);

    dim3 grid(N / BN, M / BM);
    dim3 block(256);

    // q = x @ wq + bq
    gemm_bias_act<0><<<grid, block>>>(x, wq, bq, buf0, M, N, K);
    // q_norm = LN(q)
    layernorm_kernel<<<M, 256>>>(buf0, buf1);
    // memory MLP: 3x (GEMM + SiLU), then final GEMM (no act)
    gemm_bias_act<1><<<grid, block>>>(buf1, mlp_w + 0 * DD, mlp_b + 0 * D_MODEL, buf0, M, N, K);
    gemm_bias_act<1><<<grid, block>>>(buf0, mlp_w + 1 * DD, mlp_b + 1 * D_MODEL, buf1, M, N, K);
    gemm_bias_act<1><<<grid, block>>>(buf1, mlp_w + 2 * DD, mlp_b + 2 * D_MODEL, buf0, M, N, K);
    gemm_bias_act<0><<<grid, block>>>(buf0, mlp_w + 3 * DD, mlp_b + 3 * D_MODEL, buf1, M, N, K);
    // straight-through adds exactly 0 in the forward pass -> out = h @ w_out + b_out
    gemm_bias_act<0><<<grid, block>>>(buf1, w_out, b_out, out, M, N, K);
}